// round 6
// baseline (speedup 1.0000x reference)
#include <cuda_runtime.h>
#include <mma.h>
#include <math.h>
#include <stdint.h>

using namespace nvcuda;

#define TOTPTS 16384
#define MROWS  131072   // TOT*NV
#define KDIM   2048
#define NDIM   512

// Static device scratch (no runtime allocation allowed).
__device__ float g_Xr[(size_t)MROWS * KDIM];       // tf32-RN-rounded X, 1GB
__device__ float g_W0r[(size_t)KDIM * NDIM];       // tf32-RN-rounded W0, 4MB
__device__ float g_part[(size_t)4 * MROWS * 32];   // per-N-chunk partial B32, 64MB
__device__ float g_B32[(size_t)MROWS * 32];        // bott after if1 + dirfeat, 16MB

__device__ __forceinline__ float eluf(float x) { return x > 0.f ? x : expm1f(x); }
__device__ __forceinline__ float sigm(float x) { return 1.f / (1.f + expf(-x)); }
__device__ __forceinline__ float wrsum(float v) {
#pragma unroll
    for (int o = 16; o > 0; o >>= 1) v += __shfl_xor_sync(0xffffffffu, v, o);
    return v;
}
__device__ __forceinline__ float rnd_tf32(float x) {
    float r;
    asm("cvt.rna.tf32.f32 %0, %1;" : "=f"(r) : "f"(x));
    return r;
}

__device__ __forceinline__ void cp16(void* smem_dst, const void* gmem_src) {
    unsigned int s = (unsigned int)__cvta_generic_to_shared(smem_dst);
    asm volatile("cp.async.cg.shared.global [%0], [%1], 16;\n" :: "r"(s), "l"(gmem_src));
}
__device__ __forceinline__ void cp_commit() { asm volatile("cp.async.commit_group;\n"); }
template <int N>
__device__ __forceinline__ void cp_wait() { asm volatile("cp.async.wait_group %0;\n" :: "n"(N)); }

// ---------------------------------------------------------------------------
// PREP: RN-round X and W0 to tf32 once (removes all rounding from mainloop).
// ---------------------------------------------------------------------------
__global__ void __launch_bounds__(256) prep_x(const float* __restrict__ X) {
    size_t i = ((size_t)blockIdx.x * 256 + threadIdx.x) * 4;
    const size_t total = (size_t)MROWS * KDIM;
    const size_t stride = (size_t)gridDim.x * 1024;
    for (; i < total; i += stride) {
        float4 v = *(const float4*)(X + i);
        v.x = rnd_tf32(v.x); v.y = rnd_tf32(v.y);
        v.z = rnd_tf32(v.z); v.w = rnd_tf32(v.w);
        *(float4*)(g_Xr + i) = v;
    }
}
__global__ void __launch_bounds__(256) prep_w0(const float* __restrict__ W0) {
    size_t i = ((size_t)blockIdx.x * 256 + threadIdx.x) * 4;
    if (i < (size_t)KDIM * NDIM) {
        float4 v = *(const float4*)(W0 + i);
        v.x = rnd_tf32(v.x); v.y = rnd_tf32(v.y);
        v.z = rnd_tf32(v.z); v.w = rnd_tf32(v.w);
        *(float4*)(g_W0r + i) = v;
    }
}

// ---------------------------------------------------------------------------
// GEMM1 fused (wmma tf32, operands pre-rounded in gmem — clean mainloop):
// per CTA: Htile = elu(Xr[128,2048] @ W0r[:, n0:n0+128] + b0)  (3-stage pipe)
// then partial B32 = Htile @ W1[n0:n0+128, :] -> g_part[nchunk].
// grid (4, 1024): nchunk fastest so X tiles stay L2-resident across chunks.
// ---------------------------------------------------------------------------
#define ASTRIDE 36
#define BSTRIDE 132
#define AFLOATS (128 * ASTRIDE)   // 4608
#define BFLOATS (32 * BSTRIDE)    // 4224
#define STAGEF  (AFLOATS + BFLOATS)
#define HDRF    512
#define SMEM_G1 ((HDRF + 3 * STAGEF) * 4)   // 108032 B

__device__ __forceinline__ void load_tile(float* sm, int m0, int n0, int t, int s) {
    const int k0 = t * 32;
    float* A = sm + HDRF + s * STAGEF;
    float* B = A + AFLOATS;
#pragma unroll
    for (int i = threadIdx.x; i < 1024; i += 256) {   // A: 128 x 32
        int r = i >> 3, c = (i & 7) * 4;
        cp16(&A[r * ASTRIDE + c], g_Xr + (size_t)(m0 + r) * KDIM + k0 + c);
    }
#pragma unroll
    for (int i = threadIdx.x; i < 1024; i += 256) {   // B: 32 x 128
        int r = i >> 5, c = (i & 31) * 4;
        cp16(&B[r * BSTRIDE + c], g_W0r + (size_t)(k0 + r) * NDIM + n0 + c);
    }
}

__global__ void __launch_bounds__(256, 2) gemm1_kernel(
    const float* __restrict__ b0, const float* __restrict__ W1)
{
    extern __shared__ float sm[];
    const int tid = threadIdx.x, wid = tid >> 5, lane = tid & 31;
    const int p = blockIdx.x;                  // N-chunk 0..3
    const int m0 = blockIdx.y * 128, n0 = p * 128;
    const int wm = (wid >> 1) * 32, wn = (wid & 1) * 64;

    if (tid < 128) sm[tid] = b0[n0 + tid];     // b0 chunk -> header

    wmma::fragment<wmma::accumulator, 16, 16, 8, float> acc[2][4];
#pragma unroll
    for (int i = 0; i < 2; i++)
#pragma unroll
        for (int j = 0; j < 4; j++) wmma::fill_fragment(acc[i][j], 0.f);

    // prologue: stages 0,1
    load_tile(sm, m0, n0, 0, 0); cp_commit();
    load_tile(sm, m0, n0, 1, 1); cp_commit();

    for (int t = 0; t < 64; t++) {
        const int s = t % 3;
        if (t < 63) { cp_wait<1>(); } else { cp_wait<0>(); }
        __syncthreads();

        const float* A = sm + HDRF + s * STAGEF;
        const float* B = A + AFLOATS;

#pragma unroll
        for (int kk = 0; kk < 4; kk++) {
            wmma::fragment<wmma::matrix_a, 16, 16, 8, wmma::precision::tf32, wmma::row_major> a0, a1;
            wmma::fragment<wmma::matrix_b, 16, 16, 8, wmma::precision::tf32, wmma::row_major> bf[4];
            wmma::load_matrix_sync(a0, &A[wm * ASTRIDE + kk * 8], ASTRIDE);
            wmma::load_matrix_sync(a1, &A[(wm + 16) * ASTRIDE + kk * 8], ASTRIDE);
#pragma unroll
            for (int j = 0; j < 4; j++)
                wmma::load_matrix_sync(bf[j], &B[kk * 8 * BSTRIDE + wn + j * 16], BSTRIDE);
#pragma unroll
            for (int j = 0; j < 4; j++) {
                wmma::mma_sync(acc[0][j], a0, bf[j], acc[0][j]);
                wmma::mma_sync(acc[1][j], a1, bf[j], acc[1][j]);
            }
        }

        if (t + 2 < 64) {
            load_tile(sm, m0, n0, t + 2, (t + 2) % 3);
            cp_commit();
        }
    }
    __syncthreads();

    // ---- epilogue: Hs = tf32(elu(acc + b0)); partial B32 = Hs @ W1chunk ----
    float* Hs  = sm + HDRF;            // 128 x 132
    float* W1s = sm + HDRF + 16896;    // 128 x 36  (k-major [k][n])

#pragma unroll
    for (int i = 0; i < 2; i++)
#pragma unroll
        for (int j = 0; j < 4; j++)
            wmma::store_matrix_sync(&Hs[(wm + i * 16) * BSTRIDE + wn + j * 16],
                                    acc[i][j], BSTRIDE, wmma::mem_row_major);
    // stage W1 chunk (tf32-rounded)
    for (int i = tid; i < 128 * 32; i += 256) {
        int r = i >> 5, c = i & 31;
        W1s[r * ASTRIDE + c] = rnd_tf32(W1[(size_t)(n0 + r) * 32 + c]);
    }
    __syncthreads();

    for (int i = tid; i < 128 * 128; i += 256) {
        int r = i >> 7, c = i & 127;
        float v = Hs[r * BSTRIDE + c] + sm[c];
        Hs[r * BSTRIDE + c] = rnd_tf32(eluf(v));
    }
    __syncthreads();

    {
        int r0 = wid * 16;
        wmma::fragment<wmma::accumulator, 16, 16, 8, float> oacc[2];
        wmma::fill_fragment(oacc[0], 0.f);
        wmma::fill_fragment(oacc[1], 0.f);
#pragma unroll
        for (int kk = 0; kk < 16; kk++) {
            wmma::fragment<wmma::matrix_a, 16, 16, 8, wmma::precision::tf32, wmma::row_major> af;
            wmma::fragment<wmma::matrix_b, 16, 16, 8, wmma::precision::tf32, wmma::row_major> bf0, bf1;
            wmma::load_matrix_sync(af, &Hs[r0 * BSTRIDE + kk * 8], BSTRIDE);
            wmma::load_matrix_sync(bf0, &W1s[kk * 8 * ASTRIDE], ASTRIDE);
            wmma::load_matrix_sync(bf1, &W1s[kk * 8 * ASTRIDE + 16], ASTRIDE);
            wmma::mma_sync(oacc[0], af, bf0, oacc[0]);
            wmma::mma_sync(oacc[1], af, bf1, oacc[1]);
        }
        float* dst = g_part + (size_t)p * MROWS * 32 + (size_t)(m0 + r0) * 32;
        wmma::store_matrix_sync(dst, oacc[0], 32, wmma::mem_row_major);
        wmma::store_matrix_sync(dst + 16, oacc[1], 32, wmma::mem_row_major);
    }
}

// ---------------------------------------------------------------------------
// COMBINE: B32[r,:] = sum_p part[p][r,:] + b1 + elu(rd-MLP(ray_diff[r]))
// ---------------------------------------------------------------------------
__global__ void __launch_bounds__(256) combine_kernel(
    const float* __restrict__ b1, const float* __restrict__ rdiff,
    const float* __restrict__ rd0w, const float* __restrict__ rd0b,
    const float* __restrict__ rd1w, const float* __restrict__ rd1b)
{
    const int tid = threadIdx.x, wid = tid >> 5, lane = tid & 31;
    size_t r = (size_t)blockIdx.x * 8 + wid;

    const float* rp = rdiff + r * 4;
    float rv = (lane < 4) ? rp[lane] : 0.f;
    float r0 = __shfl_sync(0xffffffffu, rv, 0), r1 = __shfl_sync(0xffffffffu, rv, 1);
    float r2 = __shfl_sync(0xffffffffu, rv, 2), r3 = __shfl_sync(0xffffffffu, rv, 3);
    float h = 0.f;
    if (lane < 16) {
        h = rd0b[lane] + r0 * rd0w[lane] + r1 * rd0w[16 + lane]
                       + r2 * rd0w[32 + lane] + r3 * rd0w[48 + lane];
        h = eluf(h);
    }
    float d = rd1b[lane];
#pragma unroll
    for (int k = 0; k < 16; k++)
        d += __shfl_sync(0xffffffffu, h, k) * rd1w[k * 32 + lane];
    d = eluf(d);

    float s = b1[lane] + d;
#pragma unroll
    for (int p = 0; p < 4; p++)
        s += g_part[(size_t)p * MROWS * 32 + r * 32 + lane];
    g_B32[r * 32 + lane] = s;
}

// ---------------------------------------------------------------------------
// STAGE2: everything after if1 — warp per point, 8 points/block.
// bf0's globalfeat half hoisted out of the view loop (view-independent).
// ---------------------------------------------------------------------------
struct WPtrs { const float* p[20]; };

#define WTOT   19432
#define WARPTMP 928

__global__ void __launch_bounds__(256) stage2_kernel(
    const float* __restrict__ tokG, const void* __restrict__ invG,
    WPtrs wp, float* __restrict__ out)
{
    extern __shared__ float sm[];
    const int tid = threadIdx.x, wid = tid >> 5, lane = tid & 31;

    const int cnt[20] = {128,8,8,1,11264,64,2048,32,1024,32,1056,33,1024,32,32,1,2080,32,512,16};
    const int off[20] = {0,128,136,144,145,11409,11473,13521,13553,14577,14609,15665,15698,16722,16754,16786,16787,18867,18899,19411};
    for (int s = 0; s < 20; s++) {
        const float* src = wp.p[s]; float* dst = sm + off[s];
        for (int i = tid; i < cnt[s]; i += 256) dst[i] = src[i];
    }
    __syncthreads();

    const float* nr0w = sm;          const float* nr0b = sm + 128;
    const float* nr1w = sm + 136;    const float* nr1b = sm + 144;
    const float* bf0w = sm + 145;    const float* bf0b = sm + 11409;
    const float* bf1w = sm + 11473;  const float* bf1b = sm + 13521;
    const float* vf0w = sm + 13553;  const float* vf0b = sm + 14577;
    const float* vf1w = sm + 14609;  const float* vf1b = sm + 15665;
    const float* v20w = sm + 15698;  const float* v20b = sm + 16722;
    const float* v21w = sm + 16754;  const float* v21b = sm + 16786;
    const float* gf0w = sm + 16787;  const float* gf0b = sm + 18867;
    const float* gf1w = sm + 18899;  const float* gf1b = sm + 19411;

    float* T = sm + WTOT + wid * WARPTMP;
    float* tokW = T;        float* bottW = T + 128;  float* xW  = T + 384;
    float* gfW  = T + 640;  float* h64W  = T + 768;  float* h33W = T + 832;
    float* wtW  = T + 872;  float* w0W   = T + 880;  float* mskW = T + 888;
    float* visW = T + 896;  float* w2W   = T + 904;

    int t = blockIdx.x * 8 + wid;

    // dtype-robust invalid_features read (uint8 vs 4-byte encodings)
    const unsigned char* bb = (const unsigned char*)invG;
    int u8f = 0;
    for (int i = lane; i < 256; i += 32) if ((i & 3) && bb[i] == 1) u8f = 1;
    u8f = (__ballot_sync(0xffffffffu, u8f) != 0);

    for (int i = lane; i < 128; i += 32) tokW[i]  = tokG[(size_t)t * 128 + i];
    for (int i = lane; i < 256; i += 32) bottW[i] = g_B32[(size_t)t * 256 + i];
    float mv = 0.f;
    if (lane < 8) {
        int idx = t * 8 + lane;
        bool inv = u8f ? (bb[idx] != 0)
                       : (((const unsigned int*)invG)[idx] != 0u);
        mv = inv ? 0.f : 1.f;
    }
    float msum = wrsum(mv);
    if (lane < 8) { mskW[lane] = mv; wtW[lane] = mv / (msum + 1e-8f); }
    __syncwarp();

    // nr: 16 -> 8 (elu) -> 1, sigmoid, * weight
    if (lane < 8) {
        float hh[8];
#pragma unroll
        for (int i = 0; i < 8; i++) hh[i] = nr0b[i];
#pragma unroll
        for (int k = 0; k < 16; k++) {
            float tv = tokW[lane * 16 + k];
#pragma unroll
            for (int i = 0; i < 8; i++) hh[i] += tv * nr0w[k * 8 + i];
        }
        float s = nr1b[0];
#pragma unroll
        for (int i = 0; i < 8; i++) s += eluf(hh[i]) * nr1w[i];
        w0W[lane] = sigm(s) * wtW[lane];
    }
    __syncwarp();

    // weighted mean/var of bott
    {
        float m0 = 0.f, m1 = 0.f;
#pragma unroll
        for (int v = 0; v < 8; v++) { float b = bottW[v * 32 + lane]; m0 += b * w0W[v]; m1 += b * wtW[v]; }
        float v0 = 0.f, v1 = 0.f;
#pragma unroll
        for (int v = 0; v < 8; v++) {
            float b = bottW[v * 32 + lane]; float d0 = b - m0, d1 = b - m1;
            v0 += w0W[v] * d0 * d0; v1 += wtW[v] * d1 * d1;
        }
        gfW[lane] = m0; gfW[32 + lane] = v0; gfW[64 + lane] = m1; gfW[96 + lane] = v1;
    }
    __syncwarp();

    // hoisted (view-independent) globalfeat half of bf0
    float gfc0 = bf0b[lane], gfc1 = bf0b[32 + lane];
#pragma unroll 8
    for (int k = 0; k < 128; k++) {
        float g = gfW[k];
        gfc0 += g * bf0w[k * 64 + lane];
        gfc1 += g * bf0w[k * 64 + 32 + lane];
    }

    for (int v = 0; v < 8; v++) {
        // bf0 per-view part: 48 inputs -> 64 (elu)
        {
            float a0 = gfc0, a1 = gfc1;
#pragma unroll
            for (int k = 0; k < 32; k++) {
                float b = bottW[v * 32 + k];
                a0 += b * bf0w[(128 + k) * 64 + lane];
                a1 += b * bf0w[(128 + k) * 64 + 32 + lane];
            }
#pragma unroll
            for (int k = 0; k < 16; k++) {
                float tv = tokW[v * 16 + k];
                a0 += tv * bf0w[(160 + k) * 64 + lane];
                a1 += tv * bf0w[(160 + k) * 64 + 32 + lane];
            }
            h64W[lane] = eluf(a0);
            h64W[32 + lane] = eluf(a1);
        }
        __syncwarp();
        // bf1: 64 -> 32 (elu)
        {
            float a = bf1b[lane];
#pragma unroll
            for (int k = 0; k < 64; k++) a += h64W[k] * bf1w[k * 32 + lane];
            xW[v * 32 + lane] = eluf(a);
        }
        __syncwarp();
        // vf on x*weight
        float wv = wtW[v];
        {
            float a = vf0b[lane];
#pragma unroll
            for (int k = 0; k < 32; k++) a += xW[v * 32 + k] * wv * vf0w[k * 32 + lane];
            h33W[lane] = eluf(a);
        }
        __syncwarp();
        float xres;
        {
            float a = vf1b[lane];
#pragma unroll
            for (int k = 0; k < 32; k++) a += h33W[k] * vf1w[k * 33 + lane];
            xres = eluf(a);
        }
        if (lane == 0) {
            float a = vf1b[32];
#pragma unroll
            for (int k = 0; k < 32; k++) a += h33W[k] * vf1w[k * 33 + 32];
            visW[v] = sigm(eluf(a)) * mskW[v];
        }
        __syncwarp();
        xW[v * 32 + lane] += xres;
        __syncwarp();
        // v2 on x*vis
        float vv = visW[v];
        {
            float a = v20b[lane];
#pragma unroll
            for (int k = 0; k < 32; k++) a += xW[v * 32 + k] * vv * v20w[k * 32 + lane];
            h33W[lane] = eluf(a);
        }
        __syncwarp();
        {
            float pr = h33W[lane] * v21w[lane];
            float s = wrsum(pr) + v21b[0];
            if (lane == 0) w2W[v] = sigm(s) * mskW[v];
        }
        __syncwarp();
    }

    {
        float vv = (lane < 8) ? w2W[lane] : 0.f;
        float s = wrsum(vv);
        if (lane < 8) w2W[lane] = vv / (s + 1e-8f);
    }
    __syncwarp();
    float wbar;
    {
        float vv = (lane < 8) ? w2W[lane] : 0.f;
        wbar = wrsum(vv) * 0.125f;
    }
    {
        float m = 0.f;
#pragma unroll
        for (int v = 0; v < 8; v++) m += xW[v * 32 + lane] * w2W[v];
        float va = 0.f;
#pragma unroll
        for (int v = 0; v < 8; v++) { float dd = xW[v * 32 + lane] - m; va += w2W[v] * dd * dd; }
        gfW[lane] = m; gfW[32 + lane] = va;
        if (lane == 0) gfW[64] = wbar;
    }
    __syncwarp();
    {
        float a = gf0b[lane];
#pragma unroll
        for (int k = 0; k < 65; k++) a += gfW[k] * gf0w[k * 32 + lane];
        h33W[lane] = eluf(a);
    }
    __syncwarp();
    if (lane < 16) {
        float a = gf1b[lane];
#pragma unroll
        for (int k = 0; k < 32; k++) a += h33W[k] * gf1w[k * 16 + lane];
        out[(size_t)t * 16 + lane] = eluf(a);
    }
}

// ---------------------------------------------------------------------------
extern "C" void kernel_launch(void* const* d_in, const int* in_sizes, int n_in,
                              void* d_out, int out_size)
{
    const float* tok   = (const float*)d_in[0];
    const float* bott  = (const float*)d_in[1];
    const float* rdiff = (const float*)d_in[2];
    const void*  inval = (const void*)d_in[3];
    const float* rd0w = (const float*)d_in[4];  const float* rd0b = (const float*)d_in[5];
    const float* rd1w = (const float*)d_in[6];  const float* rd1b = (const float*)d_in[7];
    const float* if0w = (const float*)d_in[8];  const float* if0b = (const float*)d_in[9];
    const float* if1w = (const float*)d_in[10]; const float* if1b = (const float*)d_in[11];
    float* out = (float*)d_out;

    WPtrs wp;
    for (int i = 0; i < 20; i++) wp.p[i] = (const float*)d_in[12 + i];

    const int stage2_smem = (WTOT + 8 * WARPTMP) * 4;
    cudaFuncSetAttribute(gemm1_kernel, cudaFuncAttributeMaxDynamicSharedMemorySize, SMEM_G1);
    cudaFuncSetAttribute(stage2_kernel, cudaFuncAttributeMaxDynamicSharedMemorySize, stage2_smem);

    prep_x<<<32768, 256>>>(bott);
    prep_w0<<<1024, 256>>>(if0w);
    gemm1_kernel<<<dim3(4, 1024), 256, SMEM_G1>>>(if0b, if1w);
    combine_kernel<<<MROWS / 8, 256>>>(if1b, rdiff, rd0w, rd0b, rd1w, rd1b);
    stage2_kernel<<<TOTPTS / 8, 256, stage2_smem>>>(tok, inval, wp, out);
}

// round 7
// speedup vs baseline: 1.1455x; 1.1455x over previous
#include <cuda_runtime.h>
#include <mma.h>
#include <math.h>
#include <stdint.h>

using namespace nvcuda;

#define TOTPTS 16384
#define MROWS  131072   // TOT*NV
#define KDIM   2048
#define NDIM   512

// Static device scratch (no runtime allocation allowed).
__device__ float g_W0T[(size_t)NDIM * KDIM];       // W0^T [n][k], tf32-RN, 4MB
__device__ float g_part[(size_t)4 * MROWS * 32];   // per-N-chunk partial B32, 64MB
__device__ float g_B32[(size_t)MROWS * 32];        // bott after if1 + dirfeat, 16MB

__device__ __forceinline__ float eluf(float x) { return x > 0.f ? x : expm1f(x); }
__device__ __forceinline__ float sigm(float x) { return 1.f / (1.f + expf(-x)); }
__device__ __forceinline__ float wrsum(float v) {
#pragma unroll
    for (int o = 16; o > 0; o >>= 1) v += __shfl_xor_sync(0xffffffffu, v, o);
    return v;
}
__device__ __forceinline__ float rnd_tf32(float x) {
    float r;
    asm("cvt.rna.tf32.f32 %0, %1;" : "=f"(r) : "f"(x));
    return r;
}
__device__ __forceinline__ uint32_t smem_u32(const void* p) {
    uint32_t a;
    asm("{ .reg .u64 t; cvta.to.shared.u64 t, %1; cvt.u32.u64 %0, t; }" : "=r"(a) : "l"(p));
    return a;
}
__device__ __forceinline__ void bulkcp(uint32_t dst, const void* src, uint32_t bytes,
                                       uint32_t bar) {
    asm volatile("cp.async.bulk.shared::cta.global.mbarrier::complete_tx::bytes "
                 "[%0], [%1], %2, [%3];"
                 :: "r"(dst), "l"(src), "r"(bytes), "r"(bar) : "memory");
}
__device__ __forceinline__ void ldsm4(uint32_t& r0, uint32_t& r1, uint32_t& r2, uint32_t& r3,
                                      uint32_t addr) {
    asm volatile("ldmatrix.sync.aligned.m8n8.x4.shared.b16 {%0,%1,%2,%3}, [%4];"
                 : "=r"(r0), "=r"(r1), "=r"(r2), "=r"(r3) : "r"(addr));
}
__device__ __forceinline__ void mma8(float* d, const uint32_t* a, const uint32_t* b) {
    asm volatile("mma.sync.aligned.m16n8k8.row.col.f32.tf32.tf32.f32 "
                 "{%0,%1,%2,%3}, {%4,%5,%6,%7}, {%8,%9}, {%0,%1,%2,%3};"
                 : "+f"(d[0]), "+f"(d[1]), "+f"(d[2]), "+f"(d[3])
                 : "r"(a[0]), "r"(a[1]), "r"(a[2]), "r"(a[3]), "r"(b[0]), "r"(b[1]));
}
#define MBAR_INIT(a, c) asm volatile("mbarrier.init.shared.b64 [%0], %1;" :: "r"(a), "r"(c) : "memory")
#define MBAR_EXPECT(a, tx) asm volatile("mbarrier.arrive.expect_tx.shared.b64 _, [%0], %1;" :: "r"(a), "r"(tx) : "memory")
#define MBAR_WAIT(a, ph) do {                                                              \
    uint32_t _m = (a), _p = (ph), _d;                                                      \
    asm volatile("{\n\t.reg .pred p;\n\t"                                                  \
                 "mbarrier.try_wait.parity.acquire.cta.shared::cta.b64 p, [%1], %2;\n\t"   \
                 "selp.b32 %0, 1, 0, p;\n\t}" : "=r"(_d) : "r"(_m), "r"(_p) : "memory");   \
    if (!_d) {                                                                             \
        asm volatile("{\n\t.reg .pred P1;\n\t"                                             \
            "WL%=:\n\t"                                                                    \
            "mbarrier.try_wait.parity.acquire.cta.shared::cta.b64 P1, [%0], %1, 0x989680;\n\t" \
            "@P1 bra.uni WD%=;\n\t"                                                        \
            "bra.uni WL%=;\n\t"                                                            \
            "WD%=:\n\t}" :: "r"(_m), "r"(_p) : "memory");                                  \
    }                                                                                      \
} while (0)
#define FENCE_PROXY() asm volatile("fence.proxy.async.shared::cta;" ::: "memory")

// ---------------------------------------------------------------------------
// PREP: g_W0T[n][k] = rn_tf32(W0[k][n])  (transpose + round, ~10us)
// ---------------------------------------------------------------------------
__global__ void prep_w0t(const float* __restrict__ W0) {
    __shared__ float tile[32][33];
    int n0 = blockIdx.x * 32, k0 = blockIdx.y * 32;
    int tx = threadIdx.x, ty = threadIdx.y;
#pragma unroll
    for (int j = 0; j < 32; j += 8)
        tile[ty + j][tx] = W0[(size_t)(k0 + ty + j) * NDIM + n0 + tx];
    __syncthreads();
#pragma unroll
    for (int j = 0; j < 32; j += 8)
        g_W0T[(size_t)(n0 + ty + j) * KDIM + k0 + tx] = rnd_tf32(tile[tx][ty + j]);
}

// ---------------------------------------------------------------------------
// GEMM1: raw mma.m16n8k8.tf32 + ldmatrix + cp.async.bulk 4-stage pipeline.
// Block 128x128 (grid 4 nchunks x 1024 mtiles), 8 warps, warp tile 64x32.
// Epilogue: H = tf32(elu(D+b0)) -> smem; partial B32 = H @ W1chunk (wmma).
// smem: [0..15 pad][16..47 mbarriers][byte 128..639 bias][byte1024: 4 stages
//   of (A 128rows x 144B) + (B 128rows x 144B) = 36864B each]; 148480B total.
// ---------------------------------------------------------------------------
#define STAGEB   36864
#define SMEM_G1  (1024 + 4 * STAGEB)
#define HS_F     256       // Hs float index (byte 1024), stride 132
#define W1S_F    18944     // W1s float index (byte 75776), 128x36

__global__ void __launch_bounds__(256, 1) gemm1_kernel(
    const float* __restrict__ X, const float* __restrict__ b0,
    const float* __restrict__ W1)
{
    extern __shared__ float sm[];
    const uint32_t smem = smem_u32(sm);
    const int tid = threadIdx.x, wid = tid >> 5, lane = tid & 31;
    const int p = blockIdx.x, m0 = blockIdx.y * 128, n0 = p * 128;
    const int wm = (wid >> 2) * 64, wn = (wid & 3) * 32;

    if (tid < 128) sm[32 + tid] = b0[n0 + tid];
    if (tid == 0) {
#pragma unroll
        for (int s = 0; s < 4; s++) MBAR_INIT(smem + 16 + 8 * s, 1);
        FENCE_PROXY();
    }
    __syncthreads();

    // per-thread bulk-copy row
    const bool isA = tid < 128;
    const int row = tid & 127;
    const float* srcbase = isA ? (X + (size_t)(m0 + row) * KDIM)
                               : (g_W0T + (size_t)(n0 + row) * KDIM);
    const uint32_t dsto = (isA ? 0u : 18432u) + (uint32_t)row * 144u;

    float acc[4][4][4];
#pragma unroll
    for (int g = 0; g < 4; g++)
#pragma unroll
        for (int j = 0; j < 4; j++)
#pragma unroll
            for (int e = 0; e < 4; e++) acc[g][j][e] = 0.f;

    // ldmatrix lane addressing
    const int rA = lane & 15, hA = (lane >> 4) & 1;
    const int rB = (lane & 7) + ((lane >> 4) & 1) * 8, hB = (lane >> 3) & 1;
    const uint32_t aoff = (uint32_t)(wm + rA) * 144u + (uint32_t)hA * 16u;
    const uint32_t boff = 18432u + (uint32_t)(wn + rB) * 144u + (uint32_t)hB * 16u;

    // prologue: stages 0..2
#pragma unroll
    for (int t = 0; t < 3; t++) {
        uint32_t bar = smem + 16 + 8 * t;
        if (tid == 0) MBAR_EXPECT(bar, 32768);
        __syncwarp();
        bulkcp(smem + 1024 + t * STAGEB + dsto, srcbase + t * 32, 128, bar);
    }

    for (int t = 0; t < 64; t++) {
        if (t + 3 < 64) {
            int s3 = (t + 3) & 3;
            uint32_t bar = smem + 16 + 8 * s3;
            if (tid == 0) MBAR_EXPECT(bar, 32768);
            bulkcp(smem + 1024 + s3 * STAGEB + dsto, srcbase + (t + 3) * 32, 128, bar);
        }
        const int s = t & 3;
        MBAR_WAIT(smem + 16 + 8 * s, (t >> 2) & 1);

        const uint32_t base = smem + 1024 + s * STAGEB;
#pragma unroll
        for (int ks = 0; ks < 4; ks++) {
            uint32_t a[4][4], b[2][4];
#pragma unroll
            for (int g = 0; g < 4; g++)
                ldsm4(a[g][0], a[g][1], a[g][2], a[g][3],
                      base + aoff + (uint32_t)g * 2304u + (uint32_t)ks * 32u);
#pragma unroll
            for (int jj = 0; jj < 2; jj++)
                ldsm4(b[jj][0], b[jj][1], b[jj][2], b[jj][3],
                      base + boff + (uint32_t)jj * 2304u + (uint32_t)ks * 32u);
            // RN-round A in registers (W0T pre-rounded)
#pragma unroll
            for (int g = 0; g < 4; g++)
#pragma unroll
                for (int e = 0; e < 4; e++)
                    a[g][e] = __float_as_uint(rnd_tf32(__uint_as_float(a[g][e])));
#pragma unroll
            for (int g = 0; g < 4; g++) {
                mma8(acc[g][0], a[g], &b[0][0]);
                mma8(acc[g][1], a[g], &b[0][2]);
                mma8(acc[g][2], a[g], &b[1][0]);
                mma8(acc[g][3], a[g], &b[1][2]);
            }
        }
        __syncthreads();
    }

    // ---- epilogue: Hs = tf32(elu(acc + b0)) straight from registers ----
    float* Hs  = sm + HS_F;     // 128 x 132
    float* W1s = sm + W1S_F;    // 128 x 36
    {
        const int tr = lane >> 2, tc = 2 * (lane & 3);
#pragma unroll
        for (int g = 0; g < 4; g++)
#pragma unroll
            for (int j = 0; j < 4; j++) {
                int R0 = wm + g * 16 + tr, C = wn + j * 8 + tc;
                float b0c0 = sm[32 + C], b0c1 = sm[32 + C + 1];
                float2 v0, v1;
                v0.x = rnd_tf32(eluf(acc[g][j][0] + b0c0));
                v0.y = rnd_tf32(eluf(acc[g][j][1] + b0c1));
                v1.x = rnd_tf32(eluf(acc[g][j][2] + b0c0));
                v1.y = rnd_tf32(eluf(acc[g][j][3] + b0c1));
                *(float2*)&Hs[R0 * 132 + C] = v0;
                *(float2*)&Hs[(R0 + 8) * 132 + C] = v1;
            }
    }
    // stage W1 chunk (tf32-rounded), k-major [k][n]
    for (int i = tid; i < 128 * 32; i += 256) {
        int r = i >> 5, c = i & 31;
        W1s[r * 36 + c] = rnd_tf32(W1[(size_t)(n0 + r) * 32 + c]);
    }
    __syncthreads();

    {
        int r0 = wid * 16;
        wmma::fragment<wmma::accumulator, 16, 16, 8, float> oacc[2];
        wmma::fill_fragment(oacc[0], 0.f);
        wmma::fill_fragment(oacc[1], 0.f);
#pragma unroll
        for (int kk = 0; kk < 16; kk++) {
            wmma::fragment<wmma::matrix_a, 16, 16, 8, wmma::precision::tf32, wmma::row_major> af;
            wmma::fragment<wmma::matrix_b, 16, 16, 8, wmma::precision::tf32, wmma::row_major> bf0, bf1;
            wmma::load_matrix_sync(af, &Hs[r0 * 132 + kk * 8], 132);
            wmma::load_matrix_sync(bf0, &W1s[kk * 8 * 36], 36);
            wmma::load_matrix_sync(bf1, &W1s[kk * 8 * 36 + 16], 36);
            wmma::mma_sync(oacc[0], af, bf0, oacc[0]);
            wmma::mma_sync(oacc[1], af, bf1, oacc[1]);
        }
        float* dst = g_part + (size_t)p * MROWS * 32 + (size_t)(m0 + r0) * 32;
        wmma::store_matrix_sync(dst, oacc[0], 32, wmma::mem_row_major);
        wmma::store_matrix_sync(dst + 16, oacc[1], 32, wmma::mem_row_major);
    }
}

// ---------------------------------------------------------------------------
// COMBINE: B32[r,:] = sum_p part[p][r,:] + b1 + elu(rd-MLP(ray_diff[r]))
// ---------------------------------------------------------------------------
__global__ void __launch_bounds__(256) combine_kernel(
    const float* __restrict__ b1, const float* __restrict__ rdiff,
    const float* __restrict__ rd0w, const float* __restrict__ rd0b,
    const float* __restrict__ rd1w, const float* __restrict__ rd1b)
{
    const int tid = threadIdx.x, wid = tid >> 5, lane = tid & 31;
    size_t r = (size_t)blockIdx.x * 8 + wid;

    const float* rp = rdiff + r * 4;
    float rv = (lane < 4) ? rp[lane] : 0.f;
    float r0 = __shfl_sync(0xffffffffu, rv, 0), r1 = __shfl_sync(0xffffffffu, rv, 1);
    float r2 = __shfl_sync(0xffffffffu, rv, 2), r3 = __shfl_sync(0xffffffffu, rv, 3);
    float h = 0.f;
    if (lane < 16) {
        h = rd0b[lane] + r0 * rd0w[lane] + r1 * rd0w[16 + lane]
                       + r2 * rd0w[32 + lane] + r3 * rd0w[48 + lane];
        h = eluf(h);
    }
    float d = rd1b[lane];
#pragma unroll
    for (int k = 0; k < 16; k++)
        d += __shfl_sync(0xffffffffu, h, k) * rd1w[k * 32 + lane];
    d = eluf(d);

    float s = b1[lane] + d;
#pragma unroll
    for (int p = 0; p < 4; p++)
        s += g_part[(size_t)p * MROWS * 32 + r * 32 + lane];
    g_B32[r * 32 + lane] = s;
}

// ---------------------------------------------------------------------------
// STAGE2: everything after if1 — warp per point, 8 points/block.
// ---------------------------------------------------------------------------
struct WPtrs { const float* p[20]; };

#define WTOT   19432
#define WARPTMP 928

__global__ void __launch_bounds__(256) stage2_kernel(
    const float* __restrict__ tokG, const void* __restrict__ invG,
    WPtrs wp, float* __restrict__ out)
{
    extern __shared__ float sm[];
    const int tid = threadIdx.x, wid = tid >> 5, lane = tid & 31;

    const int cnt[20] = {128,8,8,1,11264,64,2048,32,1024,32,1056,33,1024,32,32,1,2080,32,512,16};
    const int off[20] = {0,128,136,144,145,11409,11473,13521,13553,14577,14609,15665,15698,16722,16754,16786,16787,18867,18899,19411};
    for (int s = 0; s < 20; s++) {
        const float* src = wp.p[s]; float* dst = sm + off[s];
        for (int i = tid; i < cnt[s]; i += 256) dst[i] = src[i];
    }
    __syncthreads();

    const float* nr0w = sm;          const float* nr0b = sm + 128;
    const float* nr1w = sm + 136;    const float* nr1b = sm + 144;
    const float* bf0w = sm + 145;    const float* bf0b = sm + 11409;
    const float* bf1w = sm + 11473;  const float* bf1b = sm + 13521;
    const float* vf0w = sm + 13553;  const float* vf0b = sm + 14577;
    const float* vf1w = sm + 14609;  const float* vf1b = sm + 15665;
    const float* v20w = sm + 15698;  const float* v20b = sm + 16722;
    const float* v21w = sm + 16754;  const float* v21b = sm + 16786;
    const float* gf0w = sm + 16787;  const float* gf0b = sm + 18867;
    const float* gf1w = sm + 18899;  const float* gf1b = sm + 19411;

    float* T = sm + WTOT + wid * WARPTMP;
    float* tokW = T;        float* bottW = T + 128;  float* xW  = T + 384;
    float* gfW  = T + 640;  float* h64W  = T + 768;  float* h33W = T + 832;
    float* wtW  = T + 872;  float* w0W   = T + 880;  float* mskW = T + 888;
    float* visW = T + 896;  float* w2W   = T + 904;

    int t = blockIdx.x * 8 + wid;

    // dtype-robust invalid_features read (uint8 vs 4-byte encodings)
    const unsigned char* bb = (const unsigned char*)invG;
    int u8f = 0;
    for (int i = lane; i < 256; i += 32) if ((i & 3) && bb[i] == 1) u8f = 1;
    u8f = (__ballot_sync(0xffffffffu, u8f) != 0);

    for (int i = lane; i < 128; i += 32) tokW[i]  = tokG[(size_t)t * 128 + i];
    for (int i = lane; i < 256; i += 32) bottW[i] = g_B32[(size_t)t * 256 + i];
    float mv = 0.f;
    if (lane < 8) {
        int idx = t * 8 + lane;
        bool inv = u8f ? (bb[idx] != 0)
                       : (((const unsigned int*)invG)[idx] != 0u);
        mv = inv ? 0.f : 1.f;
    }
    float msum = wrsum(mv);
    if (lane < 8) { mskW[lane] = mv; wtW[lane] = mv / (msum + 1e-8f); }
    __syncwarp();

    if (lane < 8) {
        float hh[8];
#pragma unroll
        for (int i = 0; i < 8; i++) hh[i] = nr0b[i];
#pragma unroll
        for (int k = 0; k < 16; k++) {
            float tv = tokW[lane * 16 + k];
#pragma unroll
            for (int i = 0; i < 8; i++) hh[i] += tv * nr0w[k * 8 + i];
        }
        float s = nr1b[0];
#pragma unroll
        for (int i = 0; i < 8; i++) s += eluf(hh[i]) * nr1w[i];
        w0W[lane] = sigm(s) * wtW[lane];
    }
    __syncwarp();

    {
        float m0 = 0.f, m1 = 0.f;
#pragma unroll
        for (int v = 0; v < 8; v++) { float b = bottW[v * 32 + lane]; m0 += b * w0W[v]; m1 += b * wtW[v]; }
        float v0 = 0.f, v1 = 0.f;
#pragma unroll
        for (int v = 0; v < 8; v++) {
            float b = bottW[v * 32 + lane]; float d0 = b - m0, d1 = b - m1;
            v0 += w0W[v] * d0 * d0; v1 += wtW[v] * d1 * d1;
        }
        gfW[lane] = m0; gfW[32 + lane] = v0; gfW[64 + lane] = m1; gfW[96 + lane] = v1;
    }
    __syncwarp();

    float gfc0 = bf0b[lane], gfc1 = bf0b[32 + lane];
#pragma unroll 8
    for (int k = 0; k < 128; k++) {
        float g = gfW[k];
        gfc0 += g * bf0w[k * 64 + lane];
        gfc1 += g * bf0w[k * 64 + 32 + lane];
    }

    for (int v = 0; v < 8; v++) {
        {
            float a0 = gfc0, a1 = gfc1;
#pragma unroll
            for (int k = 0; k < 32; k++) {
                float b = bottW[v * 32 + k];
                a0 += b * bf0w[(128 + k) * 64 + lane];
                a1 += b * bf0w[(128 + k) * 64 + 32 + lane];
            }
#pragma unroll
            for (int k = 0; k < 16; k++) {
                float tv = tokW[v * 16 + k];
                a0 += tv * bf0w[(160 + k) * 64 + lane];
                a1 += tv * bf0w[(160 + k) * 64 + 32 + lane];
            }
            h64W[lane] = eluf(a0);
            h64W[32 + lane] = eluf(a1);
        }
        __syncwarp();
        {
            float a = bf1b[lane];
#pragma unroll
            for (int k = 0; k < 64; k++) a += h64W[k] * bf1w[k * 32 + lane];
            xW[v * 32 + lane] = eluf(a);
        }
        __syncwarp();
        float wv = wtW[v];
        {
            float a = vf0b[lane];
#pragma unroll
            for (int k = 0; k < 32; k++) a += xW[v * 32 + k] * wv * vf0w[k * 32 + lane];
            h33W[lane] = eluf(a);
        }
        __syncwarp();
        float xres;
        {
            float a = vf1b[lane];
#pragma unroll
            for (int k = 0; k < 32; k++) a += h33W[k] * vf1w[k * 33 + lane];
            xres = eluf(a);
        }
        if (lane == 0) {
            float a = vf1b[32];
#pragma unroll
            for (int k = 0; k < 32; k++) a += h33W[k] * vf1w[k * 33 + 32];
            visW[v] = sigm(eluf(a)) * mskW[v];
        }
        __syncwarp();
        xW[v * 32 + lane] += xres;
        __syncwarp();
        float vv = visW[v];
        {
            float a = v20b[lane];
#pragma unroll
            for (int k = 0; k < 32; k++) a += xW[v * 32 + k] * vv * v20w[k * 32 + lane];
            h33W[lane] = eluf(a);
        }
        __syncwarp();
        {
            float pr = h33W[lane] * v21w[lane];
            float s = wrsum(pr) + v21b[0];
            if (lane == 0) w2W[v] = sigm(s) * mskW[v];
        }
        __syncwarp();
    }

    {
        float vv = (lane < 8) ? w2W[lane] : 0.f;
        float s = wrsum(vv);
        if (lane < 8) w2W[lane] = vv / (s + 1e-8f);
    }
    __syncwarp();
    float wbar;
    {
        float vv = (lane < 8) ? w2W[lane] : 0.f;
        wbar = wrsum(vv) * 0.125f;
    }
    {
        float m = 0.f;
#pragma unroll
        for (int v = 0; v < 8; v++) m += xW[v * 32 + lane] * w2W[v];
        float va = 0.f;
#pragma unroll
        for (int v = 0; v < 8; v++) { float dd = xW[v * 32 + lane] - m; va += w2W[v] * dd * dd; }
        gfW[lane] = m; gfW[32 + lane] = va;
        if (lane == 0) gfW[64] = wbar;
    }
    __syncwarp();
    {
        float a = gf0b[lane];
#pragma unroll
        for (int k = 0; k < 65; k++) a += gfW[k] * gf0w[k * 32 + lane];
        h33W[lane] = eluf(a);
    }
    __syncwarp();
    if (lane < 16) {
        float a = gf1b[lane];
#pragma unroll
        for (int k = 0; k < 32; k++) a += h33W[k] * gf1w[k * 16 + lane];
        out[(size_t)t * 16 + lane] = eluf(a);
    }
}

// ---------------------------------------------------------------------------
extern "C" void kernel_launch(void* const* d_in, const int* in_sizes, int n_in,
                              void* d_out, int out_size)
{
    const float* tok   = (const float*)d_in[0];
    const float* bott  = (const float*)d_in[1];
    const float* rdiff = (const float*)d_in[2];
    const void*  inval = (const void*)d_in[3];
    const float* rd0w = (const float*)d_in[4];  const float* rd0b = (const float*)d_in[5];
    const float* rd1w = (const float*)d_in[6];  const float* rd1b = (const float*)d_in[7];
    const float* if0w = (const float*)d_in[8];  const float* if0b = (const float*)d_in[9];
    const float* if1w = (const float*)d_in[10]; const float* if1b = (const float*)d_in[11];
    float* out = (float*)d_out;

    WPtrs wp;
    for (int i = 0; i < 20; i++) wp.p[i] = (const float*)d_in[12 + i];

    const int stage2_smem = (WTOT + 8 * WARPTMP) * 4;
    cudaFuncSetAttribute(gemm1_kernel, cudaFuncAttributeMaxDynamicSharedMemorySize, SMEM_G1);
    cudaFuncSetAttribute(stage2_kernel, cudaFuncAttributeMaxDynamicSharedMemorySize, stage2_smem);

    prep_w0t<<<dim3(16, 64), dim3(32, 8)>>>(if0w);
    gemm1_kernel<<<dim3(4, 1024), 256, SMEM_G1>>>(bott, if0b, if1w);
    combine_kernel<<<MROWS / 8, 256>>>(if1b, rdiff, rd0w, rd0b, rd1w, rd1b);
    stage2_kernel<<<TOTPTS / 8, 256, stage2_smem>>>(tok, inval, wp, out);
}

// round 8
// speedup vs baseline: 1.8321x; 1.5994x over previous
#include <cuda_runtime.h>
#include <mma.h>
#include <math.h>
#include <stdint.h>

using namespace nvcuda;

#define TOTPTS 16384
#define MROWS  131072   // TOT*NV
#define KDIM   2048
#define NDIM   512

// Static device scratch (no runtime allocation allowed).
__device__ float g_W0T[(size_t)NDIM * KDIM];       // W0^T [n][k], tf32-RN, 4MB
__device__ float g_part[(size_t)4 * MROWS * 32];   // per-N-chunk partial B32, 64MB
__device__ float g_B32[(size_t)MROWS * 32];        // bott after if1 + dirfeat, 16MB

__device__ __forceinline__ float eluf(float x) { return x > 0.f ? x : expm1f(x); }
__device__ __forceinline__ float sigm(float x) { return 1.f / (1.f + expf(-x)); }
__device__ __forceinline__ float wrsum(float v) {
#pragma unroll
    for (int o = 16; o > 0; o >>= 1) v += __shfl_xor_sync(0xffffffffu, v, o);
    return v;
}
__device__ __forceinline__ float rnd_tf32(float x) {
    float r;
    asm("cvt.rna.tf32.f32 %0, %1;" : "=f"(r) : "f"(x));
    return r;
}
__device__ __forceinline__ uint32_t smem_u32(const void* p) {
    uint32_t a;
    asm("{ .reg .u64 t; cvta.to.shared.u64 t, %1; cvt.u32.u64 %0, t; }" : "=r"(a) : "l"(p));
    return a;
}
__device__ __forceinline__ void bulkcp(uint32_t dst, const void* src, uint32_t bytes,
                                       uint32_t bar) {
    asm volatile("cp.async.bulk.shared::cta.global.mbarrier::complete_tx::bytes "
                 "[%0], [%1], %2, [%3];"
                 :: "r"(dst), "l"(src), "r"(bytes), "r"(bar) : "memory");
}
__device__ __forceinline__ void ldsm4(uint32_t& r0, uint32_t& r1, uint32_t& r2, uint32_t& r3,
                                      uint32_t addr) {
    asm volatile("ldmatrix.sync.aligned.m8n8.x4.shared.b16 {%0,%1,%2,%3}, [%4];"
                 : "=r"(r0), "=r"(r1), "=r"(r2), "=r"(r3) : "r"(addr));
}
__device__ __forceinline__ void mma8(float* d, const uint32_t* a, const uint32_t* b) {
    asm volatile("mma.sync.aligned.m16n8k8.row.col.f32.tf32.tf32.f32 "
                 "{%0,%1,%2,%3}, {%4,%5,%6,%7}, {%8,%9}, {%0,%1,%2,%3};"
                 : "+f"(d[0]), "+f"(d[1]), "+f"(d[2]), "+f"(d[3])
                 : "r"(a[0]), "r"(a[1]), "r"(a[2]), "r"(a[3]), "r"(b[0]), "r"(b[1]));
}
#define MBAR_INIT(a, c) asm volatile("mbarrier.init.shared.b64 [%0], %1;" :: "r"(a), "r"(c) : "memory")
#define MBAR_EXPECT(a, tx) asm volatile("mbarrier.arrive.expect_tx.shared.b64 _, [%0], %1;" :: "r"(a), "r"(tx) : "memory")
#define MBAR_WAIT(a, ph) do {                                                              \
    uint32_t _m = (a), _p = (ph), _d;                                                      \
    asm volatile("{\n\t.reg .pred p;\n\t"                                                  \
                 "mbarrier.try_wait.parity.acquire.cta.shared::cta.b64 p, [%1], %2;\n\t"   \
                 "selp.b32 %0, 1, 0, p;\n\t}" : "=r"(_d) : "r"(_m), "r"(_p) : "memory");   \
    if (!_d) {                                                                             \
        asm volatile("{\n\t.reg .pred P1;\n\t"                                             \
            "WL%=:\n\t"                                                                    \
            "mbarrier.try_wait.parity.acquire.cta.shared::cta.b64 P1, [%0], %1, 0x989680;\n\t" \
            "@P1 bra.uni WD%=;\n\t"                                                        \
            "bra.uni WL%=;\n\t"                                                            \
            "WD%=:\n\t}" :: "r"(_m), "r"(_p) : "memory");                                  \
    }                                                                                      \
} while (0)
#define FENCE_PROXY() asm volatile("fence.proxy.async.shared::cta;" ::: "memory")

// ---------------------------------------------------------------------------
// PREP: g_W0T[n][k] = rn_tf32(W0[k][n])  (transpose + round, ~10us)
// ---------------------------------------------------------------------------
__global__ void prep_w0t(const float* __restrict__ W0) {
    __shared__ float tile[32][33];
    int n0 = blockIdx.x * 32, k0 = blockIdx.y * 32;
    int tx = threadIdx.x, ty = threadIdx.y;
#pragma unroll
    for (int j = 0; j < 32; j += 8)
        tile[ty + j][tx] = W0[(size_t)(k0 + ty + j) * NDIM + n0 + tx];
    __syncthreads();
#pragma unroll
    for (int j = 0; j < 32; j += 8)
        g_W0T[(size_t)(n0 + ty + j) * KDIM + k0 + tx] = rnd_tf32(tile[tx][ty + j]);
}

// ---------------------------------------------------------------------------
// GEMM1: raw mma.m16n8k8.tf32 + ldmatrix + cp.async.bulk 2-stage pipeline.
// Block 128x128 (grid 4 nchunks x 1024 mtiles), 8 warps, warp tile 64x32,
// 2 CTAs/SM so the co-resident CTA covers sync/copy stalls.
// Epilogue: H = tf32(elu(D+b0)) -> smem; partial B32 = H @ W1chunk (wmma).
// smem: [0..15 pad][16..31 mbarriers][byte 128..639 bias][byte 1024: 2 stages
//   of (A 128x144B)+(B 128x144B)=36864B each | epilogue Hs 128x132f + W1s].
// ---------------------------------------------------------------------------
#define STAGEB   36864
#define SMEM_G1  88064
#define HS_F     256       // Hs float index (byte 1024), stride 132, 128 rows
#define W1S_F    17152     // W1s float index (byte 68608), 128x36

__global__ void __launch_bounds__(256, 2) gemm1_kernel(
    const float* __restrict__ X, const float* __restrict__ b0,
    const float* __restrict__ W1)
{
    extern __shared__ float sm[];
    const uint32_t smem = smem_u32(sm);
    const int tid = threadIdx.x, wid = tid >> 5, lane = tid & 31;
    const int p = blockIdx.x, m0 = blockIdx.y * 128, n0 = p * 128;
    const int wm = (wid >> 2) * 64, wn = (wid & 3) * 32;

    if (tid < 128) sm[32 + tid] = b0[n0 + tid];
    if (tid == 0) {
        MBAR_INIT(smem + 16, 1);
        MBAR_INIT(smem + 24, 1);
        FENCE_PROXY();
    }
    __syncthreads();

    // per-thread bulk-copy row
    const bool isA = tid < 128;
    const int row = tid & 127;
    const float* srcbase = isA ? (X + (size_t)(m0 + row) * KDIM)
                               : (g_W0T + (size_t)(n0 + row) * KDIM);
    const uint32_t dsto = (isA ? 0u : 18432u) + (uint32_t)row * 144u;

    float acc[4][4][4];
#pragma unroll
    for (int g = 0; g < 4; g++)
#pragma unroll
        for (int j = 0; j < 4; j++)
#pragma unroll
            for (int e = 0; e < 4; e++) acc[g][j][e] = 0.f;

    // ldmatrix lane addressing
    const int rA = lane & 15, hA = (lane >> 4) & 1;
    const int rB = (lane & 7) + ((lane >> 4) & 1) * 8, hB = (lane >> 3) & 1;
    const uint32_t aoff = (uint32_t)(wm + rA) * 144u + (uint32_t)hA * 16u;
    const uint32_t boff = 18432u + (uint32_t)(wn + rB) * 144u + (uint32_t)hB * 16u;

    // prologue: stages 0,1
#pragma unroll
    for (int t = 0; t < 2; t++) {
        uint32_t bar = smem + 16 + 8 * t;
        if (tid == 0) MBAR_EXPECT(bar, 32768);
        __syncwarp();
        bulkcp(smem + 1024 + t * STAGEB + dsto, srcbase + t * 32, 128, bar);
    }

    for (int t = 0; t < 64; t++) {
        const int s = t & 1;
        MBAR_WAIT(smem + 16 + 8 * s, (t >> 1) & 1);

        const uint32_t base = smem + 1024 + s * STAGEB;
#pragma unroll
        for (int ks = 0; ks < 4; ks++) {
            uint32_t a[4][4], b[2][4];
#pragma unroll
            for (int g = 0; g < 4; g++)
                ldsm4(a[g][0], a[g][1], a[g][2], a[g][3],
                      base + aoff + (uint32_t)g * 2304u + (uint32_t)ks * 32u);
#pragma unroll
            for (int jj = 0; jj < 2; jj++)
                ldsm4(b[jj][0], b[jj][1], b[jj][2], b[jj][3],
                      base + boff + (uint32_t)jj * 2304u + (uint32_t)ks * 32u);
            // RN-round A in registers (W0T pre-rounded)
#pragma unroll
            for (int g = 0; g < 4; g++)
#pragma unroll
                for (int e = 0; e < 4; e++)
                    a[g][e] = __float_as_uint(rnd_tf32(__uint_as_float(a[g][e])));
#pragma unroll
            for (int g = 0; g < 4; g++) {
                mma8(acc[g][0], a[g], &b[0][0]);
                mma8(acc[g][1], a[g], &b[0][2]);
                mma8(acc[g][2], a[g], &b[1][0]);
                mma8(acc[g][3], a[g], &b[1][2]);
            }
        }
        __syncthreads();   // all warps done with stage s before refilling it
        if (t + 2 < 64) {
            uint32_t bar = smem + 16 + 8 * s;
            if (tid == 0) MBAR_EXPECT(bar, 32768);
            bulkcp(smem + 1024 + s * STAGEB + dsto, srcbase + (t + 2) * 32, 128, bar);
        }
    }

    // ---- epilogue: Hs = tf32(elu(acc + b0)) straight from registers ----
    float* Hs  = sm + HS_F;     // 128 x 132
    float* W1s = sm + W1S_F;    // 128 x 36
    {
        const int tr = lane >> 2, tc = 2 * (lane & 3);
#pragma unroll
        for (int g = 0; g < 4; g++)
#pragma unroll
            for (int j = 0; j < 4; j++) {
                int R0 = wm + g * 16 + tr, C = wn + j * 8 + tc;
                float b0c0 = sm[32 + C], b0c1 = sm[32 + C + 1];
                float2 v0, v1;
                v0.x = rnd_tf32(eluf(acc[g][j][0] + b0c0));
                v0.y = rnd_tf32(eluf(acc[g][j][1] + b0c1));
                v1.x = rnd_tf32(eluf(acc[g][j][2] + b0c0));
                v1.y = rnd_tf32(eluf(acc[g][j][3] + b0c1));
                *(float2*)&Hs[R0 * 132 + C] = v0;
                *(float2*)&Hs[(R0 + 8) * 132 + C] = v1;
            }
    }
    // stage W1 chunk (tf32-rounded), k-major [k][n]
    for (int i = tid; i < 128 * 32; i += 256) {
        int r = i >> 5, c = i & 31;
        W1s[r * 36 + c] = rnd_tf32(W1[(size_t)(n0 + r) * 32 + c]);
    }
    __syncthreads();

    {
        int r0 = wid * 16;
        wmma::fragment<wmma::accumulator, 16, 16, 8, float> oacc[2];
        wmma::fill_fragment(oacc[0], 0.f);
        wmma::fill_fragment(oacc[1], 0.f);
#pragma unroll
        for (int kk = 0; kk < 16; kk++) {
            wmma::fragment<wmma::matrix_a, 16, 16, 8, wmma::precision::tf32, wmma::row_major> af;
            wmma::fragment<wmma::matrix_b, 16, 16, 8, wmma::precision::tf32, wmma::row_major> bf0, bf1;
            wmma::load_matrix_sync(af, &Hs[r0 * 132 + kk * 8], 132);
            wmma::load_matrix_sync(bf0, &W1s[kk * 8 * 36], 36);
            wmma::load_matrix_sync(bf1, &W1s[kk * 8 * 36 + 16], 36);
            wmma::mma_sync(oacc[0], af, bf0, oacc[0]);
            wmma::mma_sync(oacc[1], af, bf1, oacc[1]);
        }
        float* dst = g_part + (size_t)p * MROWS * 32 + (size_t)(m0 + r0) * 32;
        wmma::store_matrix_sync(dst, oacc[0], 32, wmma::mem_row_major);
        wmma::store_matrix_sync(dst + 16, oacc[1], 32, wmma::mem_row_major);
    }
}

// ---------------------------------------------------------------------------
// COMBINE: B32[r,:] = sum_p part[p][r,:] + b1 + elu(rd-MLP(ray_diff[r]))
// ---------------------------------------------------------------------------
__global__ void __launch_bounds__(256) combine_kernel(
    const float* __restrict__ b1, const float* __restrict__ rdiff,
    const float* __restrict__ rd0w, const float* __restrict__ rd0b,
    const float* __restrict__ rd1w, const float* __restrict__ rd1b)
{
    const int tid = threadIdx.x, wid = tid >> 5, lane = tid & 31;
    size_t r = (size_t)blockIdx.x * 8 + wid;

    const float* rp = rdiff + r * 4;
    float rv = (lane < 4) ? rp[lane] : 0.f;
    float r0 = __shfl_sync(0xffffffffu, rv, 0), r1 = __shfl_sync(0xffffffffu, rv, 1);
    float r2 = __shfl_sync(0xffffffffu, rv, 2), r3 = __shfl_sync(0xffffffffu, rv, 3);
    float h = 0.f;
    if (lane < 16) {
        h = rd0b[lane] + r0 * rd0w[lane] + r1 * rd0w[16 + lane]
                       + r2 * rd0w[32 + lane] + r3 * rd0w[48 + lane];
        h = eluf(h);
    }
    float d = rd1b[lane];
#pragma unroll
    for (int k = 0; k < 16; k++)
        d += __shfl_sync(0xffffffffu, h, k) * rd1w[k * 32 + lane];
    d = eluf(d);

    float s = b1[lane] + d;
#pragma unroll
    for (int p = 0; p < 4; p++)
        s += g_part[(size_t)p * MROWS * 32 + r * 32 + lane];
    g_B32[r * 32 + lane] = s;
}

// ---------------------------------------------------------------------------
// STAGE2: everything after if1 — warp per point, 8 points/block.
// bf0w (45KB) stays in GLOBAL (read via __ldg) to cut smem -> 3 blocks/SM.
// ---------------------------------------------------------------------------
struct WPtrs { const float* p[20]; };

#define WTOT   8168
#define WARPTMP 928

__global__ void __launch_bounds__(256) stage2_kernel(
    const float* __restrict__ tokG, const void* __restrict__ invG,
    WPtrs wp, float* __restrict__ out)
{
    extern __shared__ float sm[];
    const int tid = threadIdx.x, wid = tid >> 5, lane = tid & 31;

    // weights -> smem (bf0w EXCLUDED; stays global)
    const int srcidx[19] = {0,1,2,3,5,6,7,8,9,10,11,12,13,14,15,16,17,18,19};
    const int cnt[19] = {128,8,8,1,64,2048,32,1024,32,1056,33,1024,32,32,1,2080,32,512,16};
    const int off[19] = {0,128,136,144,145,209,2257,2289,3313,3345,4401,4434,5458,5490,5522,5523,7603,7635,8147};
    for (int s = 0; s < 19; s++) {
        const float* src = wp.p[srcidx[s]]; float* dst = sm + off[s];
        for (int i = tid; i < cnt[s]; i += 256) dst[i] = src[i];
    }
    __syncthreads();

    const float* nr0w = sm;          const float* nr0b = sm + 128;
    const float* nr1w = sm + 136;    const float* nr1b = sm + 144;
    const float* bf0wg = wp.p[4];    // GLOBAL
    const float* bf0b = sm + 145;
    const float* bf1w = sm + 209;    const float* bf1b = sm + 2257;
    const float* vf0w = sm + 2289;   const float* vf0b = sm + 3313;
    const float* vf1w = sm + 3345;   const float* vf1b = sm + 4401;
    const float* v20w = sm + 4434;   const float* v20b = sm + 5458;
    const float* v21w = sm + 5490;   const float* v21b = sm + 5522;
    const float* gf0w = sm + 5523;   const float* gf0b = sm + 7603;
    const float* gf1w = sm + 7635;   const float* gf1b = sm + 8147;

    float* T = sm + WTOT + wid * WARPTMP;
    float* tokW = T;        float* bottW = T + 128;  float* xW  = T + 384;
    float* gfW  = T + 640;  float* h64W  = T + 768;  float* h33W = T + 832;
    float* wtW  = T + 872;  float* w0W   = T + 880;  float* mskW = T + 888;
    float* visW = T + 896;  float* w2W   = T + 904;

    int t = blockIdx.x * 8 + wid;

    // dtype-robust invalid_features read (uint8 vs 4-byte encodings)
    const unsigned char* bb = (const unsigned char*)invG;
    int u8f = 0;
    for (int i = lane; i < 256; i += 32) if ((i & 3) && bb[i] == 1) u8f = 1;
    u8f = (__ballot_sync(0xffffffffu, u8f) != 0);

    for (int i = lane; i < 128; i += 32) tokW[i]  = tokG[(size_t)t * 128 + i];
    for (int i = lane; i < 256; i += 32) bottW[i] = g_B32[(size_t)t * 256 + i];
    float mv = 0.f;
    if (lane < 8) {
        int idx = t * 8 + lane;
        bool inv = u8f ? (bb[idx] != 0)
                       : (((const unsigned int*)invG)[idx] != 0u);
        mv = inv ? 0.f : 1.f;
    }
    float msum = wrsum(mv);
    if (lane < 8) { mskW[lane] = mv; wtW[lane] = mv / (msum + 1e-8f); }
    __syncwarp();

    if (lane < 8) {
        float hh[8];
#pragma unroll
        for (int i = 0; i < 8; i++) hh[i] = nr0b[i];
#pragma unroll
        for (int k = 0; k < 16; k++) {
            float tv = tokW[lane * 16 + k];
#pragma unroll
            for (int i = 0; i < 8; i++) hh[i] += tv * nr0w[k * 8 + i];
        }
        float s = nr1b[0];
#pragma unroll
        for (int i = 0; i < 8; i++) s += eluf(hh[i]) * nr1w[i];
        w0W[lane] = sigm(s) * wtW[lane];
    }
    __syncwarp();

    {
        float m0 = 0.f, m1 = 0.f;
#pragma unroll
        for (int v = 0; v < 8; v++) { float b = bottW[v * 32 + lane]; m0 += b * w0W[v]; m1 += b * wtW[v]; }
        float v0 = 0.f, v1 = 0.f;
#pragma unroll
        for (int v = 0; v < 8; v++) {
            float b = bottW[v * 32 + lane]; float d0 = b - m0, d1 = b - m1;
            v0 += w0W[v] * d0 * d0; v1 += wtW[v] * d1 * d1;
        }
        gfW[lane] = m0; gfW[32 + lane] = v0; gfW[64 + lane] = m1; gfW[96 + lane] = v1;
    }
    __syncwarp();

    // hoisted (view-independent) globalfeat half of bf0 (weights from GLOBAL)
    float gfc0 = bf0b[lane], gfc1 = bf0b[32 + lane];
#pragma unroll 8
    for (int k = 0; k < 128; k++) {
        float g = gfW[k];
        gfc0 += g * __ldg(&bf0wg[k * 64 + lane]);
        gfc1 += g * __ldg(&bf0wg[k * 64 + 32 + lane]);
    }

    for (int v = 0; v < 8; v++) {
        {
            float a0 = gfc0, a1 = gfc1;
#pragma unroll
            for (int k = 0; k < 32; k++) {
                float b = bottW[v * 32 + k];
                a0 += b * __ldg(&bf0wg[(128 + k) * 64 + lane]);
                a1 += b * __ldg(&bf0wg[(128 + k) * 64 + 32 + lane]);
            }
#pragma unroll
            for (int k = 0; k < 16; k++) {
                float tv = tokW[v * 16 + k];
                a0 += tv * __ldg(&bf0wg[(160 + k) * 64 + lane]);
                a1 += tv * __ldg(&bf0wg[(160 + k) * 64 + 32 + lane]);
            }
            h64W[lane] = eluf(a0);
            h64W[32 + lane] = eluf(a1);
        }
        __syncwarp();
        {
            float a = bf1b[lane];
#pragma unroll
            for (int k = 0; k < 64; k++) a += h64W[k] * bf1w[k * 32 + lane];
            xW[v * 32 + lane] = eluf(a);
        }
        __syncwarp();
        float wv = wtW[v];
        {
            float a = vf0b[lane];
#pragma unroll
            for (int k = 0; k < 32; k++) a += xW[v * 32 + k] * wv * vf0w[k * 32 + lane];
            h33W[lane] = eluf(a);
        }
        __syncwarp();
        float xres;
        {
            float a = vf1b[lane];
#pragma unroll
            for (int k = 0; k < 32; k++) a += h33W[k] * vf1w[k * 33 + lane];
            xres = eluf(a);
        }
        if (lane == 0) {
            float a = vf1b[32];
#pragma unroll
            for (int k = 0; k < 32; k++) a += h33W[k] * vf1w[k * 33 + 32];
            visW[v] = sigm(eluf(a)) * mskW[v];
        }
        __syncwarp();
        xW[v * 32 + lane] += xres;
        __syncwarp();
        float vv = visW[v];
        {
            float a = v20b[lane];
#pragma unroll
            for (int k = 0; k < 32; k++) a += xW[v * 32 + k] * vv * v20w[k * 32 + lane];
            h33W[lane] = eluf(a);
        }
        __syncwarp();
        {
            float pr = h33W[lane] * v21w[lane];
            float s = wrsum(pr) + v21b[0];
            if (lane == 0) w2W[v] = sigm(s) * mskW[v];
        }
        __syncwarp();
    }

    {
        float vv = (lane < 8) ? w2W[lane] : 0.f;
        float s = wrsum(vv);
        if (lane < 8) w2W[lane] = vv / (s + 1e-8f);
    }
    __syncwarp();
    float wbar;
    {
        float vv = (lane < 8) ? w2W[lane] : 0.f;
        wbar = wrsum(vv) * 0.125f;
    }
    {
        float m = 0.f;
#pragma unroll
        for (int v = 0; v < 8; v++) m += xW[v * 32 + lane] * w2W[v];
        float va = 0.f;
#pragma unroll
        for (int v = 0; v < 8; v++) { float dd = xW[v * 32 + lane] - m; va += w2W[v] * dd * dd; }
        gfW[lane] = m; gfW[32 + lane] = va;
        if (lane == 0) gfW[64] = wbar;
    }
    __syncwarp();
    {
        float a = gf0b[lane];
#pragma unroll
        for (int k = 0; k < 65; k++) a += gfW[k] * gf0w[k * 32 + lane];
        h33W[lane] = eluf(a);
    }
    __syncwarp();
    if (lane < 16) {
        float a = gf1b[lane];
#pragma unroll
        for (int k = 0; k < 32; k++) a += h33W[k] * gf1w[k * 16 + lane];
        out[(size_t)t * 16 + lane] = eluf(a);
    }
}

// ---------------------------------------------------------------------------
extern "C" void kernel_launch(void* const* d_in, const int* in_sizes, int n_in,
                              void* d_out, int out_size)
{
    const float* tok   = (const float*)d_in[0];
    const float* bott  = (const float*)d_in[1];
    const float* rdiff = (const float*)d_in[2];
    const void*  inval = (const void*)d_in[3];
    const float* rd0w = (const float*)d_in[4];  const float* rd0b = (const float*)d_in[5];
    const float* rd1w = (const float*)d_in[6];  const float* rd1b = (const float*)d_in[7];
    const float* if0w = (const float*)d_in[8];  const float* if0b = (const float*)d_in[9];
    const float* if1w = (const float*)d_in[10]; const float* if1b = (const float*)d_in[11];
    float* out = (float*)d_out;

    WPtrs wp;
    for (int i = 0; i < 20; i++) wp.p[i] = (const float*)d_in[12 + i];

    const int stage2_smem = (WTOT + 8 * WARPTMP) * 4;
    cudaFuncSetAttribute(gemm1_kernel, cudaFuncAttributeMaxDynamicSharedMemorySize, SMEM_G1);
    cudaFuncSetAttribute(stage2_kernel, cudaFuncAttributeMaxDynamicSharedMemorySize, stage2_smem);

    prep_w0t<<<dim3(16, 64), dim3(32, 8)>>>(if0w);
    gemm1_kernel<<<dim3(4, 1024), 256, SMEM_G1>>>(bott, if0b, if1w);
    combine_kernel<<<MROWS / 8, 256>>>(if1b, rdiff, rd0w, rd0b, rd1w, rd1b);
    stage2_kernel<<<TOTPTS / 8, 256, stage2_smem>>>(tok, inval, wp, out);
}

// round 9
// speedup vs baseline: 1.8923x; 1.0329x over previous
#include <cuda_runtime.h>
#include <mma.h>
#include <math.h>
#include <stdint.h>

using namespace nvcuda;

#define TOTPTS 16384
#define MROWS  131072   // TOT*NV
#define KDIM   2048
#define NDIM   512

// Static device scratch (no runtime allocation allowed).
__device__ float g_W0T[(size_t)NDIM * KDIM];       // W0^T [n][k], tf32-RN, 4MB
__device__ float g_part[(size_t)4 * MROWS * 32];   // per-N-chunk partial B32, 64MB

__device__ __forceinline__ float eluf(float x) { return x > 0.f ? x : expm1f(x); }
__device__ __forceinline__ float sigm(float x) { return 1.f / (1.f + expf(-x)); }
__device__ __forceinline__ float wrsum(float v) {
#pragma unroll
    for (int o = 16; o > 0; o >>= 1) v += __shfl_xor_sync(0xffffffffu, v, o);
    return v;
}
__device__ __forceinline__ float rnd_tf32(float x) {
    float r;
    asm("cvt.rna.tf32.f32 %0, %1;" : "=f"(r) : "f"(x));
    return r;
}
__device__ __forceinline__ uint32_t smem_u32(const void* p) {
    uint32_t a;
    asm("{ .reg .u64 t; cvta.to.shared.u64 t, %1; cvt.u32.u64 %0, t; }" : "=r"(a) : "l"(p));
    return a;
}
__device__ __forceinline__ void bulkcp(uint32_t dst, const void* src, uint32_t bytes,
                                       uint32_t bar) {
    asm volatile("cp.async.bulk.shared::cta.global.mbarrier::complete_tx::bytes "
                 "[%0], [%1], %2, [%3];"
                 :: "r"(dst), "l"(src), "r"(bytes), "r"(bar) : "memory");
}
__device__ __forceinline__ void ldsm4(uint32_t& r0, uint32_t& r1, uint32_t& r2, uint32_t& r3,
                                      uint32_t addr) {
    asm volatile("ldmatrix.sync.aligned.m8n8.x4.shared.b16 {%0,%1,%2,%3}, [%4];"
                 : "=r"(r0), "=r"(r1), "=r"(r2), "=r"(r3) : "r"(addr));
}
__device__ __forceinline__ void mma8(float* d, const uint32_t* a, const uint32_t* b) {
    asm volatile("mma.sync.aligned.m16n8k8.row.col.f32.tf32.tf32.f32 "
                 "{%0,%1,%2,%3}, {%4,%5,%6,%7}, {%8,%9}, {%0,%1,%2,%3};"
                 : "+f"(d[0]), "+f"(d[1]), "+f"(d[2]), "+f"(d[3])
                 : "r"(a[0]), "r"(a[1]), "r"(a[2]), "r"(a[3]), "r"(b[0]), "r"(b[1]));
}
#define MBAR_INIT(a, c) asm volatile("mbarrier.init.shared.b64 [%0], %1;" :: "r"(a), "r"(c) : "memory")
#define MBAR_EXPECT(a, tx) asm volatile("mbarrier.arrive.expect_tx.shared.b64 _, [%0], %1;" :: "r"(a), "r"(tx) : "memory")
#define MBAR_WAIT(a, ph) do {                                                              \
    uint32_t _m = (a), _p = (ph), _d;                                                      \
    asm volatile("{\n\t.reg .pred p;\n\t"                                                  \
                 "mbarrier.try_wait.parity.acquire.cta.shared::cta.b64 p, [%1], %2;\n\t"   \
                 "selp.b32 %0, 1, 0, p;\n\t}" : "=r"(_d) : "r"(_m), "r"(_p) : "memory");   \
    if (!_d) {                                                                             \
        asm volatile("{\n\t.reg .pred P1;\n\t"                                             \
            "WL%=:\n\t"                                                                    \
            "mbarrier.try_wait.parity.acquire.cta.shared::cta.b64 P1, [%0], %1, 0x989680;\n\t" \
            "@P1 bra.uni WD%=;\n\t"                                                        \
            "bra.uni WL%=;\n\t"                                                            \
            "WD%=:\n\t}" :: "r"(_m), "r"(_p) : "memory");                                  \
    }                                                                                      \
} while (0)
#define FENCE_PROXY() asm volatile("fence.proxy.async.shared::cta;" ::: "memory")

// ---------------------------------------------------------------------------
// PREP: g_W0T[n][k] = rn_tf32(W0[k][n])
// ---------------------------------------------------------------------------
__global__ void prep_w0t(const float* __restrict__ W0) {
    __shared__ float tile[32][33];
    int n0 = blockIdx.x * 32, k0 = blockIdx.y * 32;
    int tx = threadIdx.x, ty = threadIdx.y;
#pragma unroll
    for (int j = 0; j < 32; j += 8)
        tile[ty + j][tx] = W0[(size_t)(k0 + ty + j) * NDIM + n0 + tx];
    __syncthreads();
#pragma unroll
    for (int j = 0; j < 32; j += 8)
        g_W0T[(size_t)(n0 + ty + j) * KDIM + k0 + tx] = rnd_tf32(tile[tx][ty + j]);
}

// ---------------------------------------------------------------------------
// GEMM1 (unchanged from round 8 — at legacy tensor-pipe floor).
// ---------------------------------------------------------------------------
#define STAGEB   36864
#define SMEM_G1  88064
#define HS_F     256
#define W1S_F    17152

__global__ void __launch_bounds__(256, 2) gemm1_kernel(
    const float* __restrict__ X, const float* __restrict__ b0,
    const float* __restrict__ W1)
{
    extern __shared__ float sm[];
    const uint32_t smem = smem_u32(sm);
    const int tid = threadIdx.x, wid = tid >> 5, lane = tid & 31;
    const int p = blockIdx.x, m0 = blockIdx.y * 128, n0 = p * 128;
    const int wm = (wid >> 2) * 64, wn = (wid & 3) * 32;

    if (tid < 128) sm[32 + tid] = b0[n0 + tid];
    if (tid == 0) {
        MBAR_INIT(smem + 16, 1);
        MBAR_INIT(smem + 24, 1);
        FENCE_PROXY();
    }
    __syncthreads();

    const bool isA = tid < 128;
    const int row = tid & 127;
    const float* srcbase = isA ? (X + (size_t)(m0 + row) * KDIM)
                               : (g_W0T + (size_t)(n0 + row) * KDIM);
    const uint32_t dsto = (isA ? 0u : 18432u) + (uint32_t)row * 144u;

    float acc[4][4][4];
#pragma unroll
    for (int g = 0; g < 4; g++)
#pragma unroll
        for (int j = 0; j < 4; j++)
#pragma unroll
            for (int e = 0; e < 4; e++) acc[g][j][e] = 0.f;

    const int rA = lane & 15, hA = (lane >> 4) & 1;
    const int rB = (lane & 7) + ((lane >> 4) & 1) * 8, hB = (lane >> 3) & 1;
    const uint32_t aoff = (uint32_t)(wm + rA) * 144u + (uint32_t)hA * 16u;
    const uint32_t boff = 18432u + (uint32_t)(wn + rB) * 144u + (uint32_t)hB * 16u;

#pragma unroll
    for (int t = 0; t < 2; t++) {
        uint32_t bar = smem + 16 + 8 * t;
        if (tid == 0) MBAR_EXPECT(bar, 32768);
        __syncwarp();
        bulkcp(smem + 1024 + t * STAGEB + dsto, srcbase + t * 32, 128, bar);
    }

    for (int t = 0; t < 64; t++) {
        const int s = t & 1;
        MBAR_WAIT(smem + 16 + 8 * s, (t >> 1) & 1);

        const uint32_t base = smem + 1024 + s * STAGEB;
#pragma unroll
        for (int ks = 0; ks < 4; ks++) {
            uint32_t a[4][4], b[2][4];
#pragma unroll
            for (int g = 0; g < 4; g++)
                ldsm4(a[g][0], a[g][1], a[g][2], a[g][3],
                      base + aoff + (uint32_t)g * 2304u + (uint32_t)ks * 32u);
#pragma unroll
            for (int jj = 0; jj < 2; jj++)
                ldsm4(b[jj][0], b[jj][1], b[jj][2], b[jj][3],
                      base + boff + (uint32_t)jj * 2304u + (uint32_t)ks * 32u);
#pragma unroll
            for (int g = 0; g < 4; g++)
#pragma unroll
                for (int e = 0; e < 4; e++)
                    a[g][e] = __float_as_uint(rnd_tf32(__uint_as_float(a[g][e])));
#pragma unroll
            for (int g = 0; g < 4; g++) {
                mma8(acc[g][0], a[g], &b[0][0]);
                mma8(acc[g][1], a[g], &b[0][2]);
                mma8(acc[g][2], a[g], &b[1][0]);
                mma8(acc[g][3], a[g], &b[1][2]);
            }
        }
        __syncthreads();
        if (t + 2 < 64) {
            uint32_t bar = smem + 16 + 8 * s;
            if (tid == 0) MBAR_EXPECT(bar, 32768);
            bulkcp(smem + 1024 + s * STAGEB + dsto, srcbase + (t + 2) * 32, 128, bar);
        }
    }

    float* Hs  = sm + HS_F;
    float* W1s = sm + W1S_F;
    {
        const int tr = lane >> 2, tc = 2 * (lane & 3);
#pragma unroll
        for (int g = 0; g < 4; g++)
#pragma unroll
            for (int j = 0; j < 4; j++) {
                int R0 = wm + g * 16 + tr, C = wn + j * 8 + tc;
                float b0c0 = sm[32 + C], b0c1 = sm[32 + C + 1];
                float2 v0, v1;
                v0.x = rnd_tf32(eluf(acc[g][j][0] + b0c0));
                v0.y = rnd_tf32(eluf(acc[g][j][1] + b0c1));
                v1.x = rnd_tf32(eluf(acc[g][j][2] + b0c0));
                v1.y = rnd_tf32(eluf(acc[g][j][3] + b0c1));
                *(float2*)&Hs[R0 * 132 + C] = v0;
                *(float2*)&Hs[(R0 + 8) * 132 + C] = v1;
            }
    }
    for (int i = tid; i < 128 * 32; i += 256) {
        int r = i >> 5, c = i & 31;
        W1s[r * 36 + c] = rnd_tf32(W1[(size_t)(n0 + r) * 32 + c]);
    }
    __syncthreads();

    {
        int r0 = wid * 16;
        wmma::fragment<wmma::accumulator, 16, 16, 8, float> oacc[2];
        wmma::fill_fragment(oacc[0], 0.f);
        wmma::fill_fragment(oacc[1], 0.f);
#pragma unroll
        for (int kk = 0; kk < 16; kk++) {
            wmma::fragment<wmma::matrix_a, 16, 16, 8, wmma::precision::tf32, wmma::row_major> af;
            wmma::fragment<wmma::matrix_b, 16, 16, 8, wmma::precision::tf32, wmma::row_major> bf0, bf1;
            wmma::load_matrix_sync(af, &Hs[r0 * 132 + kk * 8], 132);
            wmma::load_matrix_sync(bf0, &W1s[kk * 8 * 36], 36);
            wmma::load_matrix_sync(bf1, &W1s[kk * 8 * 36 + 16], 36);
            wmma::mma_sync(oacc[0], af, bf0, oacc[0]);
            wmma::mma_sync(oacc[1], af, bf1, oacc[1]);
        }
        float* dst = g_part + (size_t)p * MROWS * 32 + (size_t)(m0 + r0) * 32;
        wmma::store_matrix_sync(dst, oacc[0], 32, wmma::mem_row_major);
        wmma::store_matrix_sync(dst + 16, oacc[1], 32, wmma::mem_row_major);
    }
}

// ---------------------------------------------------------------------------
// STAGE2 (combine fused): bott built in-warp from g_part + b1 + rd-MLP.
// Views processed in PAIRS (weight loads shared); float4 broadcasts.
// bf0w stays in GLOBAL (__ldg).
// ---------------------------------------------------------------------------
struct WPtrs { const float* p[20]; };

#define WTOT    8820
#define WARPTMP 1008

__global__ void __launch_bounds__(256) stage2_kernel(
    const float* __restrict__ tokG, const void* __restrict__ invG,
    const float* __restrict__ rdiff, WPtrs wp,
    const float* __restrict__ rd0w_, const float* __restrict__ rd0b_,
    const float* __restrict__ rd1w_, const float* __restrict__ rd1b_,
    const float* __restrict__ b1_, float* __restrict__ out)
{
    extern __shared__ float sm[];
    const int tid = threadIdx.x, wid = tid >> 5, lane = tid & 31;

    // weights -> smem (bf0w excluded; stays global)
    const int srcidx[19] = {0,1,2,3,5,6,7,8,9,10,11,12,13,14,15,16,17,18,19};
    const int cnt[19] = {128,8,8,1,64,2048,32,1024,32,1056,33,1024,32,32,1,2080,32,512,16};
    const int off[19] = {0,128,136,144,145,209,2257,2289,3313,3345,4401,4434,5458,5490,5522,5523,7603,7635,8147};
    for (int s = 0; s < 19; s++) {
        const float* src = wp.p[srcidx[s]]; float* dst = sm + off[s];
        for (int i = tid; i < cnt[s]; i += 256) dst[i] = src[i];
    }
    for (int i = tid; i < 64;  i += 256) sm[8163 + i] = rd0w_[i];
    for (int i = tid; i < 16;  i += 256) sm[8227 + i] = rd0b_[i];
    for (int i = tid; i < 512; i += 256) sm[8243 + i] = rd1w_[i];
    for (int i = tid; i < 32;  i += 256) sm[8755 + i] = rd1b_[i];
    for (int i = tid; i < 32;  i += 256) sm[8787 + i] = b1_[i];
    __syncthreads();

    const float* nr0w = sm;          const float* nr0b = sm + 128;
    const float* nr1w = sm + 136;    const float* nr1b = sm + 144;
    const float* bf0wg = wp.p[4];    // GLOBAL
    const float* bf0b = sm + 145;
    const float* bf1w = sm + 209;    const float* bf1b = sm + 2257;
    const float* vf0w = sm + 2289;   const float* vf0b = sm + 3313;
    const float* vf1w = sm + 3345;   const float* vf1b = sm + 4401;
    const float* v20w = sm + 4434;   const float* v20b = sm + 5458;
    const float* v21w = sm + 5490;   const float* v21b = sm + 5522;
    const float* gf0w = sm + 5523;   const float* gf0b = sm + 7603;
    const float* gf1w = sm + 7635;   const float* gf1b = sm + 8147;
    const float* rd0w = sm + 8163;   const float* rd0b = sm + 8227;
    const float* rd1w = sm + 8243;   const float* rd1b = sm + 8755;
    const float* b1s  = sm + 8787;

    float* T = sm + WTOT + wid * WARPTMP;
    float* tokW = T;         float* bottW = T + 128;  float* xW   = T + 384;
    float* gfW  = T + 640;   float* h64W  = T + 768;  float* h33e = T + 896;
    float* h33o = T + 932;   float* wtW   = T + 968;  float* w0W  = T + 976;
    float* mskW = T + 984;   float* visW  = T + 992;  float* w2W  = T + 1000;

    int t = blockIdx.x * 8 + wid;

    // dtype-robust invalid_features read
    const unsigned char* bb = (const unsigned char*)invG;
    int u8f = 0;
    for (int i = lane; i < 256; i += 32) if ((i & 3) && bb[i] == 1) u8f = 1;
    u8f = (__ballot_sync(0xffffffffu, u8f) != 0);

    for (int i = lane; i < 128; i += 32) tokW[i] = tokG[(size_t)t * 128 + i];
    float mv = 0.f;
    if (lane < 8) {
        int idx = t * 8 + lane;
        bool inv = u8f ? (bb[idx] != 0)
                       : (((const unsigned int*)invG)[idx] != 0u);
        mv = inv ? 0.f : 1.f;
    }
    float msum = wrsum(mv);
    if (lane < 8) { mskW[lane] = mv; wtW[lane] = mv / (msum + 1e-8f); }

    // ---- fused combine: bott = sum_p part + b1 + elu(rd-MLP), paired views
#pragma unroll
    for (int vp = 0; vp < 4; vp++) {
        size_t rA = (size_t)t * 8 + 2 * vp, rB = rA + 1;
        float rvA = (lane < 4) ? rdiff[rA * 4 + lane] : 0.f;
        float rvB = (lane < 4) ? rdiff[rB * 4 + lane] : 0.f;
        float a0 = __shfl_sync(0xffffffffu, rvA, 0), a1 = __shfl_sync(0xffffffffu, rvA, 1);
        float a2 = __shfl_sync(0xffffffffu, rvA, 2), a3 = __shfl_sync(0xffffffffu, rvA, 3);
        float c0 = __shfl_sync(0xffffffffu, rvB, 0), c1 = __shfl_sync(0xffffffffu, rvB, 1);
        float c2 = __shfl_sync(0xffffffffu, rvB, 2), c3 = __shfl_sync(0xffffffffu, rvB, 3);
        float h0 = 0.f, h1 = 0.f;
        if (lane < 16) {
            h0 = eluf(rd0b[lane] + a0 * rd0w[lane] + a1 * rd0w[16 + lane]
                                 + a2 * rd0w[32 + lane] + a3 * rd0w[48 + lane]);
            h1 = eluf(rd0b[lane] + c0 * rd0w[lane] + c1 * rd0w[16 + lane]
                                 + c2 * rd0w[32 + lane] + c3 * rd0w[48 + lane]);
        }
        float d0 = rd1b[lane], d1 = rd1b[lane];
#pragma unroll
        for (int k = 0; k < 16; k++) {
            float w = rd1w[k * 32 + lane];
            d0 += __shfl_sync(0xffffffffu, h0, k) * w;
            d1 += __shfl_sync(0xffffffffu, h1, k) * w;
        }
        float s0 = b1s[lane] + eluf(d0), s1 = b1s[lane] + eluf(d1);
#pragma unroll
        for (int p = 0; p < 4; p++) {
            s0 += g_part[(size_t)p * MROWS * 32 + rA * 32 + lane];
            s1 += g_part[(size_t)p * MROWS * 32 + rB * 32 + lane];
        }
        bottW[2 * vp * 32 + lane] = s0;
        bottW[(2 * vp + 1) * 32 + lane] = s1;
    }
    __syncwarp();

    // nr: 16 -> 8 (elu) -> 1, sigmoid, * weight
    if (lane < 8) {
        float hh[8];
#pragma unroll
        for (int i = 0; i < 8; i++) hh[i] = nr0b[i];
#pragma unroll
        for (int k = 0; k < 16; k++) {
            float tv = tokW[lane * 16 + k];
#pragma unroll
            for (int i = 0; i < 8; i++) hh[i] += tv * nr0w[k * 8 + i];
        }
        float s = nr1b[0];
#pragma unroll
        for (int i = 0; i < 8; i++) s += eluf(hh[i]) * nr1w[i];
        w0W[lane] = sigm(s) * wtW[lane];
    }
    __syncwarp();

    // weighted mean/var of bott
    {
        float m0 = 0.f, m1 = 0.f;
#pragma unroll
        for (int v = 0; v < 8; v++) { float b = bottW[v * 32 + lane]; m0 += b * w0W[v]; m1 += b * wtW[v]; }
        float v0 = 0.f, v1 = 0.f;
#pragma unroll
        for (int v = 0; v < 8; v++) {
            float b = bottW[v * 32 + lane]; float d0 = b - m0, d1 = b - m1;
            v0 += w0W[v] * d0 * d0; v1 += wtW[v] * d1 * d1;
        }
        gfW[lane] = m0; gfW[32 + lane] = v0; gfW[64 + lane] = m1; gfW[96 + lane] = v1;
    }
    __syncwarp();

    // hoisted globalfeat half of bf0 (float4 broadcasts of gfW)
    float gfc0 = bf0b[lane], gfc1 = bf0b[32 + lane];
#pragma unroll
    for (int k4 = 0; k4 < 32; k4++) {
        float4 g4 = *(float4*)&gfW[k4 * 4];
#pragma unroll
        for (int e = 0; e < 4; e++) {
            int k = k4 * 4 + e;
            float g = (&g4.x)[e];
            gfc0 += g * __ldg(&bf0wg[k * 64 + lane]);
            gfc1 += g * __ldg(&bf0wg[k * 64 + 32 + lane]);
        }
    }

    // ---- paired view loop ----
#pragma unroll 1
    for (int vp = 0; vp < 4; vp++) {
        const int v0 = 2 * vp, v1 = v0 + 1;
        // bf0 per-view part: 48 inputs -> 64 (elu), weights shared
        {
            float a00 = gfc0, a01 = gfc1, a10 = gfc0, a11 = gfc1;
#pragma unroll
            for (int k4 = 0; k4 < 8; k4++) {
                float4 bA = *(float4*)&bottW[v0 * 32 + k4 * 4];
                float4 bB = *(float4*)&bottW[v1 * 32 + k4 * 4];
#pragma unroll
                for (int e = 0; e < 4; e++) {
                    int k = k4 * 4 + e;
                    float w0 = __ldg(&bf0wg[(128 + k) * 64 + lane]);
                    float w1 = __ldg(&bf0wg[(128 + k) * 64 + 32 + lane]);
                    float fA = (&bA.x)[e], fB = (&bB.x)[e];
                    a00 += fA * w0; a01 += fA * w1;
                    a10 += fB * w0; a11 += fB * w1;
                }
            }
#pragma unroll
            for (int k4 = 0; k4 < 4; k4++) {
                float4 tA = *(float4*)&tokW[v0 * 16 + k4 * 4];
                float4 tB = *(float4*)&tokW[v1 * 16 + k4 * 4];
#pragma unroll
                for (int e = 0; e < 4; e++) {
                    int k = k4 * 4 + e;
                    float w0 = __ldg(&bf0wg[(160 + k) * 64 + lane]);
                    float w1 = __ldg(&bf0wg[(160 + k) * 64 + 32 + lane]);
                    float fA = (&tA.x)[e], fB = (&tB.x)[e];
                    a00 += fA * w0; a01 += fA * w1;
                    a10 += fB * w0; a11 += fB * w1;
                }
            }
            h64W[lane] = eluf(a00); h64W[32 + lane] = eluf(a01);
            h64W[64 + lane] = eluf(a10); h64W[96 + lane] = eluf(a11);
        }
        __syncwarp();
        // bf1: 64 -> 32 (elu), weights shared
        {
            float s0 = bf1b[lane], s1 = bf1b[lane];
#pragma unroll
            for (int k4 = 0; k4 < 16; k4++) {
                float4 hA = *(float4*)&h64W[k4 * 4];
                float4 hB = *(float4*)&h64W[64 + k4 * 4];
#pragma unroll
                for (int e = 0; e < 4; e++) {
                    float w = bf1w[(k4 * 4 + e) * 32 + lane];
                    s0 += (&hA.x)[e] * w; s1 += (&hB.x)[e] * w;
                }
            }
            xW[v0 * 32 + lane] = eluf(s0);
            xW[v1 * 32 + lane] = eluf(s1);
        }
        __syncwarp();
        // vf0 on x*weight (factor wv out of the dot)
        const float wv0 = wtW[v0], wv1 = wtW[v1];
        {
            float dot0 = 0.f, dot1 = 0.f;
#pragma unroll
            for (int k4 = 0; k4 < 8; k4++) {
                float4 xA = *(float4*)&xW[v0 * 32 + k4 * 4];
                float4 xB = *(float4*)&xW[v1 * 32 + k4 * 4];
#pragma unroll
                for (int e = 0; e < 4; e++) {
                    float w = vf0w[(k4 * 4 + e) * 32 + lane];
                    dot0 += (&xA.x)[e] * w; dot1 += (&xB.x)[e] * w;
                }
            }
            h33e[lane] = eluf(vf0b[lane] + wv0 * dot0);
            h33o[lane] = eluf(vf0b[lane] + wv1 * dot1);
        }
        __syncwarp();
        // vf1: 32 -> 33 (elu); col 32 handled by lanes 0,1 (one view each)
        float xres0, xres1;
        {
            float d0 = vf1b[lane], d1 = vf1b[lane];
#pragma unroll
            for (int k4 = 0; k4 < 8; k4++) {
                float4 hA = *(float4*)&h33e[k4 * 4];
                float4 hB = *(float4*)&h33o[k4 * 4];
#pragma unroll
                for (int e = 0; e < 4; e++) {
                    float w = vf1w[(k4 * 4 + e) * 33 + lane];
                    d0 += (&hA.x)[e] * w; d1 += (&hB.x)[e] * w;
                }
            }
            xres0 = eluf(d0); xres1 = eluf(d1);
        }
        if (lane < 2) {
            const float* hx = h33e + lane * 36;
            float a = vf1b[32];
#pragma unroll
            for (int k = 0; k < 32; k++) a += hx[k] * vf1w[k * 33 + 32];
            visW[v0 + lane] = sigm(eluf(a)) * mskW[v0 + lane];
        }
        __syncwarp();
        xW[v0 * 32 + lane] += xres0;
        xW[v1 * 32 + lane] += xres1;
        __syncwarp();
        // v20 on x*vis
        const float vv0 = visW[v0], vv1 = visW[v1];
        {
            float dot0 = 0.f, dot1 = 0.f;
#pragma unroll
            for (int k4 = 0; k4 < 8; k4++) {
                float4 xA = *(float4*)&xW[v0 * 32 + k4 * 4];
                float4 xB = *(float4*)&xW[v1 * 32 + k4 * 4];
#pragma unroll
                for (int e = 0; e < 4; e++) {
                    float w = v20w[(k4 * 4 + e) * 32 + lane];
                    dot0 += (&xA.x)[e] * w; dot1 += (&xB.x)[e] * w;
                }
            }
            h33e[lane] = eluf(v20b[lane] + vv0 * dot0);
            h33o[lane] = eluf(v20b[lane] + vv1 * dot1);
        }
        __syncwarp();
        {
            float wv21 = v21w[lane];
            float s0 = wrsum(h33e[lane] * wv21) + v21b[0];
            float s1 = wrsum(h33o[lane] * wv21) + v21b[0];
            if (lane == 0) {
                w2W[v0] = sigm(s0) * mskW[v0];
                w2W[v1] = sigm(s1) * mskW[v1];
            }
        }
        __syncwarp();
    }

    // weight2 normalize + wbar
    {
        float vv = (lane < 8) ? w2W[lane] : 0.f;
        float s = wrsum(vv);
        if (lane < 8) w2W[lane] = vv / (s + 1e-8f);
    }
    __syncwarp();
    float wbar;
    {
        float vv = (lane < 8) ? w2W[lane] : 0.f;
        wbar = wrsum(vv) * 0.125f;
    }
    // weighted mean/var of x
    {
        float m = 0.f;
#pragma unroll
        for (int v = 0; v < 8; v++) m += xW[v * 32 + lane] * w2W[v];
        float va = 0.f;
#pragma unroll
        for (int v = 0; v < 8; v++) { float dd = xW[v * 32 + lane] - m; va += w2W[v] * dd * dd; }
        gfW[lane] = m; gfW[32 + lane] = va;
        if (lane == 0) gfW[64] = wbar;
    }
    __syncwarp();
    // gf: 65 -> 32 (elu) -> 16 (elu)
    {
        float a = gf0b[lane];
#pragma unroll
        for (int k4 = 0; k4 < 16; k4++) {
            float4 g4 = *(float4*)&gfW[k4 * 4];
#pragma unroll
            for (int e = 0; e < 4; e++)
                a += (&g4.x)[e] * gf0w[(k4 * 4 + e) * 32 + lane];
        }
        a += gfW[64] * gf0w[64 * 32 + lane];
        h33e[lane] = eluf(a);
    }
    __syncwarp();
    if (lane < 16) {
        float a = gf1b[lane];
#pragma unroll
        for (int k = 0; k < 32; k++) a += h33e[k] * gf1w[k * 16 + lane];
        out[(size_t)t * 16 + lane] = eluf(a);
    }
}

// ---------------------------------------------------------------------------
extern "C" void kernel_launch(void* const* d_in, const int* in_sizes, int n_in,
                              void* d_out, int out_size)
{
    const float* tok   = (const float*)d_in[0];
    const float* bott  = (const float*)d_in[1];
    const float* rdiff = (const float*)d_in[2];
    const void*  inval = (const void*)d_in[3];
    const float* rd0w = (const float*)d_in[4];  const float* rd0b = (const float*)d_in[5];
    const float* rd1w = (const float*)d_in[6];  const float* rd1b = (const float*)d_in[7];
    const float* if0w = (const float*)d_in[8];  const float* if0b = (const float*)d_in[9];
    const float* if1w = (const float*)d_in[10]; const float* if1b = (const float*)d_in[11];
    float* out = (float*)d_out;

    WPtrs wp;
    for (int i = 0; i < 20; i++) wp.p[i] = (const float*)d_in[12 + i];

    const int stage2_smem = (WTOT + 8 * WARPTMP) * 4;   // 67536 B
    cudaFuncSetAttribute(gemm1_kernel, cudaFuncAttributeMaxDynamicSharedMemorySize, SMEM_G1);
    cudaFuncSetAttribute(stage2_kernel, cudaFuncAttributeMaxDynamicSharedMemorySize, stage2_smem);

    prep_w0t<<<dim3(16, 64), dim3(32, 8)>>>(if0w);
    gemm1_kernel<<<dim3(4, 1024), 256, SMEM_G1>>>(bott, if0b, if1w);
    stage2_kernel<<<TOTPTS / 8, 256, stage2_smem>>>(tok, inval, rdiff, wp,
                                                    rd0w, rd0b, rd1w, rd1b, if1b, out);
}